// round 1
// baseline (speedup 1.0000x reference)
#include <cuda_runtime.h>
#include <cstdint>

// LSTM: T=128 steps, B=128 batch, I=H=1024.
// Phase 1: G = X @ [Wxf|Wxi|Wxc|Wxo] + bias   (one big GEMM, 16384x4096, K=1024)
// Phase 2: 128 sequential fused step kernels: gates = G[t] + h @ W_h*, nonlinearity,
//          c/h update, h written directly into d_out (doubles as h history).
// Phase 3: append h_T, c_T to tail of d_out if out_size has room.

constexpr int T_STEPS = 128;
constexpr int BATCH   = 128;
constexpr int IDIM    = 1024;
constexpr int HDIM    = 1024;
constexpr int NGATE   = 4 * HDIM;   // 4096

// Scratch (device globals: allocation-free per harness rules)
__device__ float g_xw[(size_t)T_STEPS * BATCH * NGATE];  // 256 MB
__device__ float g_c[BATCH * HDIM];                      // cell state

static __device__ __forceinline__ unsigned long long pack2(float lo, float hi) {
    unsigned long long r;
    asm("mov.b64 %0, {%1, %2};" : "=l"(r) : "f"(lo), "f"(hi));
    return r;
}
static __device__ __forceinline__ void unpack2(unsigned long long v, float& lo, float& hi) {
    asm("mov.b64 {%0, %1}, %2;" : "=f"(lo), "=f"(hi) : "l"(v));
}
// Packed dual-fp32 FMA (Blackwell f32x2 pipe: 2x throughput of 3-reg FFMA)
static __device__ __forceinline__ unsigned long long ffma2(
    unsigned long long a, unsigned long long b, unsigned long long c) {
    unsigned long long d;
    asm("fma.rn.f32x2 %0, %1, %2, %3;" : "=l"(d) : "l"(a), "l"(b), "l"(c));
    return d;
}

static __device__ __forceinline__ float sigmoidf_(float x) {
    return 1.0f / (1.0f + __expf(-x));
}

// ============================================================================
// Kernel 1: G[m, g*1024+u] = sum_k X[m,k] * Wx_g[k,u] + b_g[u]
// Tile: BM=128, BN=64, BK=16, 256 threads, 8x4 micro-tile per thread (f32x2 pairs)
// Grid: (4096/64, 16384/128) = (64, 128)
// ============================================================================
__global__ __launch_bounds__(256) void gemm_xw_kernel(
    const float* __restrict__ X,
    const float* __restrict__ Wf, const float* __restrict__ Wi,
    const float* __restrict__ Wc, const float* __restrict__ Wo,
    const float* __restrict__ bf, const float* __restrict__ bi,
    const float* __restrict__ bc, const float* __restrict__ bo)
{
    __shared__ float As[16][132];  // [k][m], padded
    __shared__ float Bs[16][64];   // [k][n]

    const int tid = threadIdx.x;
    const int tx = tid & 15;        // n-dir: 16 threads x 4 cols
    const int ty = tid >> 4;        // m-dir: 16 threads x 8 rows
    const int n0 = blockIdx.x * 64;
    const int m0 = blockIdx.y * 128;
    const int g  = n0 >> 10;        // 64-wide tiles never straddle a gate
    const int u0 = n0 & 1023;
    const float* W    = (g == 0) ? Wf : (g == 1) ? Wi : (g == 2) ? Wc : Wo;
    const float* bptr = (g == 0) ? bf : (g == 1) ? bi : (g == 2) ? bc : bo;

    // load-thread mappings
    const int xr = tid >> 2, xc = tid & 3;   // X: rows xr, xr+64; k-chunk xc*4
    const int wr = tid >> 4, wc = tid & 15;  // W: k-row wr, col-chunk wc*4

    const float* Xp = X + (size_t)(m0 + xr) * IDIM + xc * 4;
    const float* Wp = W + (size_t)wr * HDIM + u0 + wc * 4;

    float4 pa0 = *(const float4*)(Xp);
    float4 pa1 = *(const float4*)(Xp + (size_t)64 * IDIM);
    float4 pb  = *(const float4*)(Wp);

    unsigned long long acc[8][2];
    #pragma unroll
    for (int i = 0; i < 8; i++) { acc[i][0] = 0ull; acc[i][1] = 0ull; }

    for (int kt = 0; kt < 64; kt++) {
        // stage current prefetch into SMEM
        As[xc * 4 + 0][xr]      = pa0.x;
        As[xc * 4 + 1][xr]      = pa0.y;
        As[xc * 4 + 2][xr]      = pa0.z;
        As[xc * 4 + 3][xr]      = pa0.w;
        As[xc * 4 + 0][xr + 64] = pa1.x;
        As[xc * 4 + 1][xr + 64] = pa1.y;
        As[xc * 4 + 2][xr + 64] = pa1.z;
        As[xc * 4 + 3][xr + 64] = pa1.w;
        *(float4*)&Bs[wr][wc * 4] = pb;
        __syncthreads();

        if (kt < 63) {  // prefetch next K-slab (overlaps with compute below)
            int kk = (kt + 1) * 16;
            pa0 = *(const float4*)(Xp + kk);
            pa1 = *(const float4*)(Xp + (size_t)64 * IDIM + kk);
            pb  = *(const float4*)(Wp + (size_t)kk * HDIM);
        }

        #pragma unroll
        for (int k = 0; k < 16; k++) {
            float4 a0 = *(const float4*)&As[k][ty * 8];
            float4 a1 = *(const float4*)&As[k][ty * 8 + 4];
            float4 b  = *(const float4*)&Bs[k][tx * 4];
            unsigned long long b01 = pack2(b.x, b.y);
            unsigned long long b23 = pack2(b.z, b.w);
            float am[8] = {a0.x, a0.y, a0.z, a0.w, a1.x, a1.y, a1.z, a1.w};
            #pragma unroll
            for (int mi = 0; mi < 8; mi++) {
                unsigned long long ad = pack2(am[mi], am[mi]);
                acc[mi][0] = ffma2(ad, b01, acc[mi][0]);
                acc[mi][1] = ffma2(ad, b23, acc[mi][1]);
            }
        }
        __syncthreads();
    }

    // epilogue: add bias, store
    float bb0 = bptr[u0 + tx * 4 + 0];
    float bb1 = bptr[u0 + tx * 4 + 1];
    float bb2 = bptr[u0 + tx * 4 + 2];
    float bb3 = bptr[u0 + tx * 4 + 3];
    #pragma unroll
    for (int mi = 0; mi < 8; mi++) {
        float x0, x1, x2, x3;
        unpack2(acc[mi][0], x0, x1);
        unpack2(acc[mi][1], x2, x3);
        size_t row = (size_t)(m0 + ty * 8 + mi);
        float4 v = make_float4(x0 + bb0, x1 + bb1, x2 + bb2, x3 + bb3);
        *(float4*)&g_xw[row * NGATE + n0 + tx * 4] = v;
    }
}

// ============================================================================
// Kernel 2: one LSTM step. gates = G[t] + h @ [Whf|Whi|Whc|Who]; update c,h.
// CTA tile: 64 batch rows x 16 hidden units x 4 gates; grid (2, 64) = 128 CTAs.
// h read from d_out rows of step t-1 (zeros at t=0); h_new written to step t.
// ============================================================================
__global__ __launch_bounds__(256) void lstm_step_kernel(
    int t,
    const float* __restrict__ Whf, const float* __restrict__ Whi,
    const float* __restrict__ Whc, const float* __restrict__ Who,
    float* __restrict__ out)
{
    __shared__ float As[16][68];      // [k][m], padded
    __shared__ float Bs[16][17][4];   // [k][u][gate], padded row

    const int tid = threadIdx.x;
    const int tu = tid & 15;          // hidden unit within tile
    const int tm = tid >> 4;          // 16 groups x 4 batch rows
    const int m0 = blockIdx.x * 64;
    const int u0 = blockIdx.y * 16;

    const float* hprev = out + (size_t)(t - 1) * BATCH * HDIM;  // valid only t>0

    // load-thread mappings
    const int hr = tid >> 2, hc = tid & 3;          // h: row hr (0..63), k-chunk hc*4
    const int wg = tid >> 6;                        // gate 0..3
    const int wk = (tid & 63) >> 2, wc = tid & 3;   // W: k-row, u-chunk
    const float* Wg = (wg == 0) ? Whf : (wg == 1) ? Whi : (wg == 2) ? Whc : Who;

    const float* Hp = hprev + (size_t)(m0 + hr) * HDIM + hc * 4;
    const float* Wp = Wg + (size_t)wk * HDIM + u0 + wc * 4;

    float4 ph = make_float4(0.f, 0.f, 0.f, 0.f);
    if (t > 0) ph = *(const float4*)(Hp);
    float4 pw = *(const float4*)(Wp);

    unsigned long long acc01[4] = {0ull, 0ull, 0ull, 0ull};  // gates (f,i)
    unsigned long long acc23[4] = {0ull, 0ull, 0ull, 0ull};  // gates (c~,o)

    for (int kt = 0; kt < 64; kt++) {
        As[hc * 4 + 0][hr] = ph.x;
        As[hc * 4 + 1][hr] = ph.y;
        As[hc * 4 + 2][hr] = ph.z;
        As[hc * 4 + 3][hr] = ph.w;
        Bs[wk][wc * 4 + 0][wg] = pw.x;
        Bs[wk][wc * 4 + 1][wg] = pw.y;
        Bs[wk][wc * 4 + 2][wg] = pw.z;
        Bs[wk][wc * 4 + 3][wg] = pw.w;
        __syncthreads();

        if (kt < 63) {
            int kk = (kt + 1) * 16;
            if (t > 0) ph = *(const float4*)(Hp + kk);
            pw = *(const float4*)(Wp + (size_t)kk * HDIM);
        }

        #pragma unroll
        for (int k = 0; k < 16; k++) {
            float4 a = *(const float4*)&As[k][tm * 4];
            float4 b = *(const float4*)&Bs[k][tu][0];
            unsigned long long b01 = pack2(b.x, b.y);
            unsigned long long b23 = pack2(b.z, b.w);
            float am[4] = {a.x, a.y, a.z, a.w};
            #pragma unroll
            for (int mi = 0; mi < 4; mi++) {
                unsigned long long ad = pack2(am[mi], am[mi]);
                acc01[mi] = ffma2(ad, b01, acc01[mi]);
                acc23[mi] = ffma2(ad, b23, acc23[mi]);
            }
        }
        __syncthreads();
    }

    // epilogue: fuse G[t], nonlinearities, cell/hidden update
    const int u = u0 + tu;
    #pragma unroll
    for (int mi = 0; mi < 4; mi++) {
        int m = m0 + tm * 4 + mi;
        size_t gbase = ((size_t)t * BATCH + m) * NGATE;
        float pf, pi, pc, po;
        unpack2(acc01[mi], pf, pi);
        unpack2(acc23[mi], pc, po);
        pf += g_xw[gbase + 0 * HDIM + u];
        pi += g_xw[gbase + 1 * HDIM + u];
        pc += g_xw[gbase + 2 * HDIM + u];
        po += g_xw[gbase + 3 * HDIM + u];

        float fgate = sigmoidf_(pf);
        float igate = sigmoidf_(pi);
        float ctil  = tanhf(pc);
        float ogate = sigmoidf_(po);

        float cold = (t > 0) ? g_c[m * HDIM + u] : 0.0f;
        float cnew = fgate * cold + igate * ctil;
        float hnew = ogate * tanhf(cnew);

        g_c[m * HDIM + u] = cnew;
        out[((size_t)t * BATCH + m) * HDIM + u] = hnew;
    }
}

// ============================================================================
// Kernel 3: append h_T (= last h rows, already in out) and c_T to the tail.
// ============================================================================
__global__ void tail_kernel(float* __restrict__ out, int write_c)
{
    int idx = blockIdx.x * blockDim.x + threadIdx.x;
    if (idx >= BATCH * HDIM) return;
    size_t TBH = (size_t)T_STEPS * BATCH * HDIM;
    out[TBH + idx] = out[(size_t)(T_STEPS - 1) * BATCH * HDIM + idx];
    if (write_c) out[TBH + (size_t)BATCH * HDIM + idx] = g_c[idx];
}

// ============================================================================
extern "C" void kernel_launch(void* const* d_in, const int* in_sizes, int n_in,
                              void* d_out, int out_size)
{
    const float* X   = (const float*)d_in[0];
    const float* Wxf = (const float*)d_in[1];
    const float* Whf = (const float*)d_in[2];
    const float* bf  = (const float*)d_in[3];
    const float* Wxi = (const float*)d_in[4];
    const float* Whi = (const float*)d_in[5];
    const float* bi  = (const float*)d_in[6];
    const float* Wxc = (const float*)d_in[7];
    const float* Whc = (const float*)d_in[8];
    const float* bc  = (const float*)d_in[9];
    const float* Wxo = (const float*)d_in[10];
    const float* Who = (const float*)d_in[11];
    const float* bo  = (const float*)d_in[12];
    float* out = (float*)d_out;

    dim3 g1(NGATE / 64, (T_STEPS * BATCH) / 128);
    gemm_xw_kernel<<<g1, 256>>>(X, Wxf, Wxi, Wxc, Wxo, bf, bi, bc, bo);

    for (int t = 0; t < T_STEPS; t++) {
        lstm_step_kernel<<<dim3(2, 64), 256>>>(t, Whf, Whi, Whc, Who, out);
    }

    long long TBH  = (long long)T_STEPS * BATCH * HDIM;
    long long tail = (long long)out_size - TBH;
    if (tail >= 2LL * BATCH * HDIM) {
        tail_kernel<<<(BATCH * HDIM + 255) / 256, 256>>>(out, 1);
    } else if (tail >= (long long)BATCH * HDIM) {
        tail_kernel<<<(BATCH * HDIM + 255) / 256, 256>>>(out, 0);
    }
}

// round 3
// speedup vs baseline: 2.2533x; 2.2533x over previous
#include <cuda_runtime.h>
#include <cuda_bf16.h>
#include <cstdint>

// LSTM T=128, B=128, I=H=1024.  mma.sync (base PTX, sm_100-safe) bf16 split-precision.
// Phase 0: split X / W^T (gate-interleaved [n=u*4+g][k]) into bf16 hi/lo; bias; init.
// Phase 1: g_xw = X @ Wx + b   (3-term split-bf16 mma.sync, tiles 128x128)
// Phase 2: 128 sequential step kernels: h @ Wh + fused LSTM epilogue + h re-split.
// Phase 3: tail (h_T, c_T).

constexpr int T_STEPS = 128, BATCH = 128, HDIM = 1024, KDIM = 1024;
constexpr int TB = T_STEPS * BATCH;   // 16384
constexpr int NG = 4 * HDIM;          // 4096

// ---------------- scratch ----------------------------------------------------
__device__ __nv_bfloat16 g_Xhi[(size_t)TB * KDIM];
__device__ __nv_bfloat16 g_Xlo[(size_t)TB * KDIM];
__device__ __nv_bfloat16 g_WxThi[(size_t)NG * KDIM];
__device__ __nv_bfloat16 g_WxTlo[(size_t)NG * KDIM];
__device__ __nv_bfloat16 g_WhThi[(size_t)NG * KDIM];
__device__ __nv_bfloat16 g_WhTlo[(size_t)NG * KDIM];
__device__ float g_bias[NG];
__device__ float g_xw[(size_t)TB * NG];              // 256 MB
__device__ __nv_bfloat16 g_hhi[2][BATCH * HDIM];
__device__ __nv_bfloat16 g_hlo[2][BATCH * HDIM];
__device__ float g_c[BATCH * HDIM];

// ---------------- helpers ----------------------------------------------------
static __device__ __forceinline__ uint32_t smem_u32(const void* p) {
    uint32_t a;
    asm("{ .reg .u64 t; cvta.to.shared.u64 t, %1; cvt.u32.u64 %0, t; }" : "=r"(a) : "l"(p));
    return a;
}
static __device__ __forceinline__ void ldsm4(uint32_t addr, uint32_t& r0, uint32_t& r1,
                                             uint32_t& r2, uint32_t& r3) {
    asm volatile("ldmatrix.sync.aligned.m8n8.x4.shared.b16 {%0,%1,%2,%3}, [%4];"
                 : "=r"(r0), "=r"(r1), "=r"(r2), "=r"(r3) : "r"(addr));
}
static __device__ __forceinline__ void mma16816(float* d, const uint32_t* a,
                                                uint32_t b0, uint32_t b1) {
    asm volatile(
        "mma.sync.aligned.m16n8k16.row.col.f32.bf16.bf16.f32 "
        "{%0,%1,%2,%3},{%4,%5,%6,%7},{%8,%9},{%0,%1,%2,%3};"
        : "+f"(d[0]), "+f"(d[1]), "+f"(d[2]), "+f"(d[3])
        : "r"(a[0]), "r"(a[1]), "r"(a[2]), "r"(a[3]), "r"(b0), "r"(b1));
}
static __device__ __forceinline__ float sigmoidf_(float x) { return 1.0f / (1.0f + __expf(-x)); }

// ---------------- Phase 0 -----------------------------------------------------
__global__ void splitx_kernel(const float* __restrict__ X) {
    size_t i = ((size_t)blockIdx.x * 256 + threadIdx.x) * 4;
    float4 v = *(const float4*)(X + i);
    __nv_bfloat16 h0 = __float2bfloat16(v.x), h1 = __float2bfloat16(v.y);
    __nv_bfloat16 h2 = __float2bfloat16(v.z), h3 = __float2bfloat16(v.w);
    __nv_bfloat16 l0 = __float2bfloat16(v.x - __bfloat162float(h0));
    __nv_bfloat16 l1 = __float2bfloat16(v.y - __bfloat162float(h1));
    __nv_bfloat16 l2 = __float2bfloat16(v.z - __bfloat162float(h2));
    __nv_bfloat16 l3 = __float2bfloat16(v.w - __bfloat162float(h3));
    ((__nv_bfloat162*)(g_Xhi + i))[0] = __nv_bfloat162(h0, h1);
    ((__nv_bfloat162*)(g_Xhi + i))[1] = __nv_bfloat162(h2, h3);
    ((__nv_bfloat162*)(g_Xlo + i))[0] = __nv_bfloat162(l0, l1);
    ((__nv_bfloat162*)(g_Xlo + i))[1] = __nv_bfloat162(l2, l3);
}

__global__ void splitw_kernel(const float* __restrict__ W0, const float* __restrict__ W1,
                              const float* __restrict__ W2, const float* __restrict__ W3,
                              __nv_bfloat16* __restrict__ hiT, __nv_bfloat16* __restrict__ loT) {
    __shared__ float sm[32][33];
    const int g = blockIdx.z;
    const float* W = (g == 0) ? W0 : (g == 1) ? W1 : (g == 2) ? W2 : W3;
    const int k0 = blockIdx.x * 32, u0 = blockIdx.y * 32;
    const int tx = threadIdx.x & 31, ty = threadIdx.x >> 5;
    #pragma unroll
    for (int i = 0; i < 4; i++)
        sm[ty + 8 * i][tx] = W[(size_t)(k0 + ty + 8 * i) * HDIM + u0 + tx];
    __syncthreads();
    #pragma unroll
    for (int i = 0; i < 4; i++) {
        int ul = ty + 8 * i;
        float v = sm[tx][ul];
        __nv_bfloat16 h = __float2bfloat16(v);
        __nv_bfloat16 l = __float2bfloat16(v - __bfloat162float(h));
        size_t n = (size_t)(u0 + ul) * 4 + g;
        hiT[n * KDIM + k0 + tx] = h;
        loT[n * KDIM + k0 + tx] = l;
    }
}

__global__ void bias_kernel(const float* __restrict__ bf, const float* __restrict__ bi,
                            const float* __restrict__ bc, const float* __restrict__ bo) {
    int u = blockIdx.x * 256 + threadIdx.x;
    g_bias[u * 4 + 0] = bf[u];
    g_bias[u * 4 + 1] = bi[u];
    g_bias[u * 4 + 2] = bc[u];
    g_bias[u * 4 + 3] = bo[u];
}

__global__ void init_kernel() {
    int i = blockIdx.x * 256 + threadIdx.x;
    if (i < BATCH * HDIM) {
        g_hhi[0][i] = __float2bfloat16(0.0f);
        g_hlo[0][i] = __float2bfloat16(0.0f);
        g_c[i] = 0.0f;
    }
}

// ---------------- Phase 1: GEMM1 ---------------------------------------------
// Tile M=128, N=128, KC=32. 256 threads = 8 warps (4 m x 2 n), warp tile 32x64.
constexpr int G1_SA = 40;   // A smem stride (elems)
constexpr int G1_SB = 40;
constexpr int G1_A_HI = 0;
constexpr int G1_A_LO = 128 * G1_SA * 2;              // 10240
constexpr int G1_B_HI = G1_A_LO + 128 * G1_SA * 2;    // 20480
constexpr int G1_B_LO = G1_B_HI + 128 * G1_SB * 2;    // 30720
constexpr int G1_SMEM = G1_B_LO + 128 * G1_SB * 2;    // 40960

__global__ __launch_bounds__(256)
void gemm1_kernel() {
    extern __shared__ char smem[];
    const uint32_t sb = smem_u32(smem);
    const int tid = threadIdx.x, wid = tid >> 5, l = tid & 31;
    const int wm = wid & 3, wn = wid >> 2;
    const int n0 = blockIdx.x * 128, m0 = blockIdx.y * 128;

    // loader mapping: A/B tiles are 128 rows x 32 cols bf16 (64B/row = 4 chunks)
    const int lr = tid >> 2, lc = tid & 3;   // rows lr, lr+64 ; 16B chunk lc
    uint4 pah[2], pal[2], pbh[2], pbl[2];
    auto ld_chunk = [&](int kc) {
        #pragma unroll
        for (int i = 0; i < 2; i++) {
            size_t ra = (size_t)(m0 + lr + 64 * i) * KDIM + kc * 32 + lc * 8;
            size_t rb = (size_t)(n0 + lr + 64 * i) * KDIM + kc * 32 + lc * 8;
            pah[i] = *(const uint4*)(g_Xhi + ra);
            pal[i] = *(const uint4*)(g_Xlo + ra);
            pbh[i] = *(const uint4*)(g_WxThi + rb);
            pbl[i] = *(const uint4*)(g_WxTlo + rb);
        }
    };
    ld_chunk(0);

    // ldmatrix lane addresses (byte offsets into tile), kk advances +32B
    // A frag (m16k16): row = mbase + (l&15), col = (l>>4)*8
    uint32_t aoff[2];
    #pragma unroll
    for (int mb = 0; mb < 2; mb++)
        aoff[mb] = ((wm * 32 + mb * 16 + (l & 15)) * G1_SA + (l >> 4) * 8) * 2;
    // B frag x4 (n16,k16): row = nbase + (l&7) + (l>>4)*8, col = ((l>>3)&1)*8
    uint32_t boff[4];
    #pragma unroll
    for (int nbp = 0; nbp < 4; nbp++)
        boff[nbp] = ((wn * 64 + nbp * 16 + (l & 7) + (l >> 4) * 8) * G1_SB +
                     ((l >> 3) & 1) * 8) * 2;

    float acc[2][4][2][4];
    #pragma unroll
    for (int a = 0; a < 2; a++)
        #pragma unroll
        for (int b = 0; b < 4; b++)
            #pragma unroll
            for (int c = 0; c < 2; c++)
                #pragma unroll
                for (int d = 0; d < 4; d++) acc[a][b][c][d] = 0.f;

    const int smst = lr * G1_SA * 2 + lc * 16;  // store offset within a tile half
    for (int kc = 0; kc < 32; kc++) {
        #pragma unroll
        for (int i = 0; i < 2; i++) {
            int o = smst + i * 64 * G1_SA * 2;
            *(uint4*)(smem + G1_A_HI + o) = pah[i];
            *(uint4*)(smem + G1_A_LO + o) = pal[i];
            *(uint4*)(smem + G1_B_HI + o) = pbh[i];
            *(uint4*)(smem + G1_B_LO + o) = pbl[i];
        }
        __syncthreads();
        if (kc < 31) ld_chunk(kc + 1);

        #pragma unroll
        for (int kk = 0; kk < 2; kk++) {
            uint32_t ah[2][4], al[2][4];
            #pragma unroll
            for (int mb = 0; mb < 2; mb++) {
                ldsm4(sb + G1_A_HI + aoff[mb] + kk * 32, ah[mb][0], ah[mb][1], ah[mb][2], ah[mb][3]);
                ldsm4(sb + G1_A_LO + aoff[mb] + kk * 32, al[mb][0], al[mb][1], al[mb][2], al[mb][3]);
            }
            #pragma unroll
            for (int nbp = 0; nbp < 4; nbp++) {
                uint32_t bh0, bh1, bh2, bh3, bl0, bl1, bl2, bl3;
                ldsm4(sb + G1_B_HI + boff[nbp] + kk * 32, bh0, bh1, bh2, bh3);
                ldsm4(sb + G1_B_LO + boff[nbp] + kk * 32, bl0, bl1, bl2, bl3);
                #pragma unroll
                for (int mb = 0; mb < 2; mb++) {
                    mma16816(acc[mb][nbp][0], ah[mb], bh0, bh1);
                    mma16816(acc[mb][nbp][0], al[mb], bh0, bh1);
                    mma16816(acc[mb][nbp][0], ah[mb], bl0, bl1);
                    mma16816(acc[mb][nbp][1], ah[mb], bh2, bh3);
                    mma16816(acc[mb][nbp][1], al[mb], bh2, bh3);
                    mma16816(acc[mb][nbp][1], ah[mb], bl2, bl3);
                }
            }
        }
        __syncthreads();
    }

    // epilogue: bias + store (float2 per accum pair)
    #pragma unroll
    for (int mb = 0; mb < 2; mb++) {
        #pragma unroll
        for (int nbp = 0; nbp < 4; nbp++) {
            #pragma unroll
            for (int nb = 0; nb < 2; nb++) {
                int n = n0 + wn * 64 + nbp * 16 + nb * 8 + (l & 3) * 2;
                float2 bz = *(const float2*)(g_bias + n);
                int m = m0 + wm * 32 + mb * 16 + (l >> 2);
                float* p0 = g_xw + (size_t)m * NG + n;
                float* p1 = g_xw + (size_t)(m + 8) * NG + n;
                *(float2*)p0 = make_float2(acc[mb][nbp][nb][0] + bz.x, acc[mb][nbp][nb][1] + bz.y);
                *(float2*)p1 = make_float2(acc[mb][nbp][nb][2] + bz.x, acc[mb][nbp][nb][3] + bz.y);
            }
        }
    }
}

// ---------------- Phase 2: step kernel ----------------------------------------
// Tile M=128 (all batch), N=32, KC=64. 8 warps (4 m x 2 n), warp tile 32x16.
constexpr int S_SA = 72;   // smem stride (elems)
constexpr int S_A_HI = 0;
constexpr int S_A_LO = 128 * S_SA * 2;            // 18432
constexpr int S_B_HI = S_A_LO + 128 * S_SA * 2;   // 36864
constexpr int S_B_LO = S_B_HI + 32 * S_SA * 2;    // 41472
constexpr int S_SMEM = S_B_LO + 32 * S_SA * 2;    // 46080
constexpr int PRE_S = 36;                          // epilogue pre stride (floats)

__global__ __launch_bounds__(256)
void lstm_step_kernel(int t, float* __restrict__ out) {
    extern __shared__ char smem[];
    const uint32_t sb = smem_u32(smem);
    const int tid = threadIdx.x, wid = tid >> 5, l = tid & 31;
    const int wm = wid & 3, wn = wid >> 2;
    const int n0 = blockIdx.x * 32;

    const __nv_bfloat16* Ahi = g_hhi[t & 1];
    const __nv_bfloat16* Alo = g_hlo[t & 1];

    // loaders: A 128x64 (8 chunks/row, 32 rows/pass x4), B 32x64 (1 pass)
    const int ar = tid >> 3, ac = tid & 7;
    uint4 pah[4], pal[4], pbh, pbl;
    auto ld_chunk = [&](int kc) {
        #pragma unroll
        for (int i = 0; i < 4; i++) {
            size_t ra = (size_t)(ar + 32 * i) * KDIM + kc * 64 + ac * 8;
            pah[i] = *(const uint4*)(Ahi + ra);
            pal[i] = *(const uint4*)(Alo + ra);
        }
        size_t rb = (size_t)(n0 + ar) * KDIM + kc * 64 + ac * 8;
        pbh = *(const uint4*)(g_WhThi + rb);
        pbl = *(const uint4*)(g_WhTlo + rb);
    };
    ld_chunk(0);

    uint32_t aoff[2];
    #pragma unroll
    for (int mb = 0; mb < 2; mb++)
        aoff[mb] = ((wm * 32 + mb * 16 + (l & 15)) * S_SA + (l >> 4) * 8) * 2;
    uint32_t boff = ((wn * 16 + (l & 7) + (l >> 4) * 8) * S_SA + ((l >> 3) & 1) * 8) * 2;

    float acc[2][2][4];
    #pragma unroll
    for (int a = 0; a < 2; a++)
        #pragma unroll
        for (int b = 0; b < 2; b++)
            #pragma unroll
            for (int d = 0; d < 4; d++) acc[a][b][d] = 0.f;

    const int smst = ar * S_SA * 2 + ac * 16;
    for (int kc = 0; kc < 16; kc++) {
        #pragma unroll
        for (int i = 0; i < 4; i++) {
            int o = smst + i * 32 * S_SA * 2;
            *(uint4*)(smem + S_A_HI + o) = pah[i];
            *(uint4*)(smem + S_A_LO + o) = pal[i];
        }
        *(uint4*)(smem + S_B_HI + smst) = pbh;
        *(uint4*)(smem + S_B_LO + smst) = pbl;
        __syncthreads();
        if (kc < 15) ld_chunk(kc + 1);

        #pragma unroll
        for (int kk = 0; kk < 4; kk++) {
            uint32_t ah[2][4], al[2][4];
            #pragma unroll
            for (int mb = 0; mb < 2; mb++) {
                ldsm4(sb + S_A_HI + aoff[mb] + kk * 32, ah[mb][0], ah[mb][1], ah[mb][2], ah[mb][3]);
                ldsm4(sb + S_A_LO + aoff[mb] + kk * 32, al[mb][0], al[mb][1], al[mb][2], al[mb][3]);
            }
            uint32_t bh0, bh1, bh2, bh3, bl0, bl1, bl2, bl3;
            ldsm4(sb + S_B_HI + boff + kk * 32, bh0, bh1, bh2, bh3);
            ldsm4(sb + S_B_LO + boff + kk * 32, bl0, bl1, bl2, bl3);
            #pragma unroll
            for (int mb = 0; mb < 2; mb++) {
                mma16816(acc[mb][0], ah[mb], bh0, bh1);
                mma16816(acc[mb][0], al[mb], bh0, bh1);
                mma16816(acc[mb][0], ah[mb], bl0, bl1);
                mma16816(acc[mb][1], ah[mb], bh2, bh3);
                mma16816(acc[mb][1], al[mb], bh2, bh3);
                mma16816(acc[mb][1], ah[mb], bl2, bl3);
            }
        }
        __syncthreads();
    }

    // dump preactivations to smem (reuse A region), then fused LSTM epilogue
    float* pre = (float*)smem;
    #pragma unroll
    for (int mb = 0; mb < 2; mb++) {
        #pragma unroll
        for (int nb = 0; nb < 2; nb++) {
            int row = wm * 32 + mb * 16 + (l >> 2);
            int col = wn * 16 + nb * 8 + (l & 3) * 2;
            *(float2*)(pre + row * PRE_S + col) = make_float2(acc[mb][nb][0], acc[mb][nb][1]);
            *(float2*)(pre + (row + 8) * PRE_S + col) = make_float2(acc[mb][nb][2], acc[mb][nb][3]);
        }
    }
    __syncthreads();

    const int wbuf = (t + 1) & 1;
    #pragma unroll
    for (int i = 0; i < 4; i++) {
        int cell = tid + 256 * i;        // 1024 cells: 128 m x 8 units
        int m = cell >> 3, ul = cell & 7;
        float4 pa = *(const float4*)(pre + m * PRE_S + ul * 4);
        float4 gx = *(const float4*)(g_xw + ((size_t)t * BATCH + m) * NG + n0 + ul * 4);
        float pf = pa.x + gx.x, pi = pa.y + gx.y, pc = pa.z + gx.z, po = pa.w + gx.w;
        float fg = sigmoidf_(pf);
        float ig = sigmoidf_(pi);
        float ct = tanhf(pc);
        float og = sigmoidf_(po);
        int u = (n0 >> 2) + ul;
        int cu = m * HDIM + u;
        float cn = fg * g_c[cu] + ig * ct;
        float hn = og * tanhf(cn);
        g_c[cu] = cn;
        out[((size_t)t * BATCH + m) * HDIM + u] = hn;
        __nv_bfloat16 hh = __float2bfloat16(hn);
        __nv_bfloat16 hl = __float2bfloat16(hn - __bfloat162float(hh));
        g_hhi[wbuf][cu] = hh;
        g_hlo[wbuf][cu] = hl;
    }
}

// ---------------- Phase 3: tail -----------------------------------------------
__global__ void tail_kernel(float* __restrict__ out, int write_c) {
    int idx = blockIdx.x * blockDim.x + threadIdx.x;
    if (idx >= BATCH * HDIM) return;
    size_t TBH = (size_t)T_STEPS * BATCH * HDIM;
    out[TBH + idx] = out[(size_t)(T_STEPS - 1) * BATCH * HDIM + idx];
    if (write_c) out[TBH + (size_t)BATCH * HDIM + idx] = g_c[idx];
}

// ---------------- launch ------------------------------------------------------
extern "C" void kernel_launch(void* const* d_in, const int* in_sizes, int n_in,
                              void* d_out, int out_size)
{
    const float* X   = (const float*)d_in[0];
    const float* Wxf = (const float*)d_in[1];
    const float* Whf = (const float*)d_in[2];
    const float* bf  = (const float*)d_in[3];
    const float* Wxi = (const float*)d_in[4];
    const float* Whi = (const float*)d_in[5];
    const float* bi  = (const float*)d_in[6];
    const float* Wxc = (const float*)d_in[7];
    const float* Whc = (const float*)d_in[8];
    const float* bc  = (const float*)d_in[9];
    const float* Wxo = (const float*)d_in[10];
    const float* Who = (const float*)d_in[11];
    const float* bo  = (const float*)d_in[12];
    float* out = (float*)d_out;

    __nv_bfloat16 *wxhi, *wxlo, *whhi, *whlo;
    cudaGetSymbolAddress((void**)&wxhi, g_WxThi);
    cudaGetSymbolAddress((void**)&wxlo, g_WxTlo);
    cudaGetSymbolAddress((void**)&whhi, g_WhThi);
    cudaGetSymbolAddress((void**)&whlo, g_WhTlo);

    cudaFuncSetAttribute(gemm1_kernel, cudaFuncAttributeMaxDynamicSharedMemorySize, G1_SMEM);
    cudaFuncSetAttribute(lstm_step_kernel, cudaFuncAttributeMaxDynamicSharedMemorySize, S_SMEM);

    splitx_kernel<<<(TB * KDIM) / 1024, 256>>>(X);
    splitw_kernel<<<dim3(32, 32, 4), 256>>>(Wxf, Wxi, Wxc, Wxo, wxhi, wxlo);
    splitw_kernel<<<dim3(32, 32, 4), 256>>>(Whf, Whi, Whc, Who, whhi, whlo);
    bias_kernel<<<4, 256>>>(bf, bi, bc, bo);
    init_kernel<<<(BATCH * HDIM + 255) / 256, 256>>>();

    gemm1_kernel<<<dim3(NG / 128, TB / 128), 256, G1_SMEM>>>();

    for (int t = 0; t < T_STEPS; t++)
        lstm_step_kernel<<<NG / 32, 256, S_SMEM>>>(t, out);

    long long TBH  = (long long)T_STEPS * BATCH * HDIM;
    long long tail = (long long)out_size - TBH;
    if (tail >= 2LL * BATCH * HDIM) {
        tail_kernel<<<(BATCH * HDIM + 255) / 256, 256>>>(out, 1);
    } else if (tail >= (long long)BATCH * HDIM) {
        tail_kernel<<<(BATCH * HDIM + 255) / 256, 256>>>(out, 0);
    }
}

// round 4
// speedup vs baseline: 2.5161x; 1.1166x over previous
#include <cuda_runtime.h>
#include <cuda_bf16.h>
#include <cstdint>

// LSTM T=128, B=128, I=H=1024.  mma.sync bf16 split-precision (3-term).
// Phase 0: split X / W^T (gate-interleaved [n=u*4+g][k]) into bf16 hi/lo; bias; init.
// Phase 1: g_xw = X @ Wx + b   (tiles 128x128)
// Phase 2: ONE persistent kernel, 128 CTAs, grid barrier per step. Each CTA keeps
//          its Wh slice (32 gate-cols, hi+lo) resident in SMEM for all 128 steps.
// Tail (h_T, c_T) folded into the last step's epilogue.

constexpr int T_STEPS = 128, BATCH = 128, HDIM = 1024, KDIM = 1024;
constexpr int TB = T_STEPS * BATCH;   // 16384
constexpr int NG = 4 * HDIM;          // 4096
constexpr int NCTA = 128;             // persistent grid

// ---------------- scratch ----------------------------------------------------
__device__ __nv_bfloat16 g_Xhi[(size_t)TB * KDIM];
__device__ __nv_bfloat16 g_Xlo[(size_t)TB * KDIM];
__device__ __nv_bfloat16 g_WxThi[(size_t)NG * KDIM];
__device__ __nv_bfloat16 g_WxTlo[(size_t)NG * KDIM];
__device__ __nv_bfloat16 g_WhThi[(size_t)NG * KDIM];
__device__ __nv_bfloat16 g_WhTlo[(size_t)NG * KDIM];
__device__ float g_bias[NG];
__device__ float g_xw[(size_t)TB * NG];              // 256 MB
__device__ __nv_bfloat16 g_hhi[2][BATCH * HDIM];
__device__ __nv_bfloat16 g_hlo[2][BATCH * HDIM];
__device__ float g_c[BATCH * HDIM];
__device__ unsigned g_bar;

// ---------------- helpers ----------------------------------------------------
static __device__ __forceinline__ uint32_t smem_u32(const void* p) {
    uint32_t a;
    asm("{ .reg .u64 t; cvta.to.shared.u64 t, %1; cvt.u32.u64 %0, t; }" : "=r"(a) : "l"(p));
    return a;
}
static __device__ __forceinline__ void ldsm4(uint32_t addr, uint32_t& r0, uint32_t& r1,
                                             uint32_t& r2, uint32_t& r3) {
    asm volatile("ldmatrix.sync.aligned.m8n8.x4.shared.b16 {%0,%1,%2,%3}, [%4];"
                 : "=r"(r0), "=r"(r1), "=r"(r2), "=r"(r3) : "r"(addr));
}
static __device__ __forceinline__ void mma16816(float* d, const uint32_t* a,
                                                uint32_t b0, uint32_t b1) {
    asm volatile(
        "mma.sync.aligned.m16n8k16.row.col.f32.bf16.bf16.f32 "
        "{%0,%1,%2,%3},{%4,%5,%6,%7},{%8,%9},{%0,%1,%2,%3};"
        : "+f"(d[0]), "+f"(d[1]), "+f"(d[2]), "+f"(d[3])
        : "r"(a[0]), "r"(a[1]), "r"(a[2]), "r"(a[3]), "r"(b0), "r"(b1));
}
static __device__ __forceinline__ uint4 ldcg4(const void* p) {
    uint4 v;
    asm volatile("ld.global.cg.v4.u32 {%0,%1,%2,%3}, [%4];"
                 : "=r"(v.x), "=r"(v.y), "=r"(v.z), "=r"(v.w) : "l"(p));
    return v;
}
static __device__ __forceinline__ float sigmoidf_(float x) { return 1.0f / (1.0f + __expf(-x)); }

// ---------------- Phase 0 -----------------------------------------------------
__global__ void splitx_kernel(const float* __restrict__ X) {
    size_t i = ((size_t)blockIdx.x * 256 + threadIdx.x) * 4;
    float4 v = *(const float4*)(X + i);
    __nv_bfloat16 h0 = __float2bfloat16(v.x), h1 = __float2bfloat16(v.y);
    __nv_bfloat16 h2 = __float2bfloat16(v.z), h3 = __float2bfloat16(v.w);
    __nv_bfloat16 l0 = __float2bfloat16(v.x - __bfloat162float(h0));
    __nv_bfloat16 l1 = __float2bfloat16(v.y - __bfloat162float(h1));
    __nv_bfloat16 l2 = __float2bfloat16(v.z - __bfloat162float(h2));
    __nv_bfloat16 l3 = __float2bfloat16(v.w - __bfloat162float(h3));
    ((__nv_bfloat162*)(g_Xhi + i))[0] = __nv_bfloat162(h0, h1);
    ((__nv_bfloat162*)(g_Xhi + i))[1] = __nv_bfloat162(h2, h3);
    ((__nv_bfloat162*)(g_Xlo + i))[0] = __nv_bfloat162(l0, l1);
    ((__nv_bfloat162*)(g_Xlo + i))[1] = __nv_bfloat162(l2, l3);
}

__global__ void splitw_kernel(const float* __restrict__ W0, const float* __restrict__ W1,
                              const float* __restrict__ W2, const float* __restrict__ W3,
                              __nv_bfloat16* __restrict__ hiT, __nv_bfloat16* __restrict__ loT) {
    __shared__ float sm[32][33];
    const int g = blockIdx.z;
    const float* W = (g == 0) ? W0 : (g == 1) ? W1 : (g == 2) ? W2 : W3;
    const int k0 = blockIdx.x * 32, u0 = blockIdx.y * 32;
    const int tx = threadIdx.x & 31, ty = threadIdx.x >> 5;
    #pragma unroll
    for (int i = 0; i < 4; i++)
        sm[ty + 8 * i][tx] = W[(size_t)(k0 + ty + 8 * i) * HDIM + u0 + tx];
    __syncthreads();
    #pragma unroll
    for (int i = 0; i < 4; i++) {
        int ul = ty + 8 * i;
        float v = sm[tx][ul];
        __nv_bfloat16 h = __float2bfloat16(v);
        __nv_bfloat16 l = __float2bfloat16(v - __bfloat162float(h));
        size_t n = (size_t)(u0 + ul) * 4 + g;
        hiT[n * KDIM + k0 + tx] = h;
        loT[n * KDIM + k0 + tx] = l;
    }
}

__global__ void bias_kernel(const float* __restrict__ bf, const float* __restrict__ bi,
                            const float* __restrict__ bc, const float* __restrict__ bo) {
    int u = blockIdx.x * 256 + threadIdx.x;
    g_bias[u * 4 + 0] = bf[u];
    g_bias[u * 4 + 1] = bi[u];
    g_bias[u * 4 + 2] = bc[u];
    g_bias[u * 4 + 3] = bo[u];
    if (u == 0) g_bar = 0;
}

// ---------------- Phase 1: GEMM1 (unchanged from R3) -------------------------
constexpr int G1_SA = 40;
constexpr int G1_SB = 40;
constexpr int G1_A_HI = 0;
constexpr int G1_A_LO = 128 * G1_SA * 2;
constexpr int G1_B_HI = G1_A_LO + 128 * G1_SA * 2;
constexpr int G1_B_LO = G1_B_HI + 128 * G1_SB * 2;
constexpr int G1_SMEM = G1_B_LO + 128 * G1_SB * 2;    // 40960

__global__ __launch_bounds__(256)
void gemm1_kernel() {
    extern __shared__ char smem[];
    const uint32_t sb = smem_u32(smem);
    const int tid = threadIdx.x, wid = tid >> 5, l = tid & 31;
    const int wm = wid & 3, wn = wid >> 2;
    const int n0 = blockIdx.x * 128, m0 = blockIdx.y * 128;

    const int lr = tid >> 2, lc = tid & 3;
    uint4 pah[2], pal[2], pbh[2], pbl[2];
    auto ld_chunk = [&](int kc) {
        #pragma unroll
        for (int i = 0; i < 2; i++) {
            size_t ra = (size_t)(m0 + lr + 64 * i) * KDIM + kc * 32 + lc * 8;
            size_t rb = (size_t)(n0 + lr + 64 * i) * KDIM + kc * 32 + lc * 8;
            pah[i] = *(const uint4*)(g_Xhi + ra);
            pal[i] = *(const uint4*)(g_Xlo + ra);
            pbh[i] = *(const uint4*)(g_WxThi + rb);
            pbl[i] = *(const uint4*)(g_WxTlo + rb);
        }
    };
    ld_chunk(0);

    uint32_t aoff[2];
    #pragma unroll
    for (int mb = 0; mb < 2; mb++)
        aoff[mb] = ((wm * 32 + mb * 16 + (l & 15)) * G1_SA + (l >> 4) * 8) * 2;
    uint32_t boff[4];
    #pragma unroll
    for (int nbp = 0; nbp < 4; nbp++)
        boff[nbp] = ((wn * 64 + nbp * 16 + (l & 7) + (l >> 4) * 8) * G1_SB +
                     ((l >> 3) & 1) * 8) * 2;

    float acc[2][4][2][4];
    #pragma unroll
    for (int a = 0; a < 2; a++)
        #pragma unroll
        for (int b = 0; b < 4; b++)
            #pragma unroll
            for (int c = 0; c < 2; c++)
                #pragma unroll
                for (int d = 0; d < 4; d++) acc[a][b][c][d] = 0.f;

    const int smst = lr * G1_SA * 2 + lc * 16;
    for (int kc = 0; kc < 32; kc++) {
        #pragma unroll
        for (int i = 0; i < 2; i++) {
            int o = smst + i * 64 * G1_SA * 2;
            *(uint4*)(smem + G1_A_HI + o) = pah[i];
            *(uint4*)(smem + G1_A_LO + o) = pal[i];
            *(uint4*)(smem + G1_B_HI + o) = pbh[i];
            *(uint4*)(smem + G1_B_LO + o) = pbl[i];
        }
        __syncthreads();
        if (kc < 31) ld_chunk(kc + 1);

        #pragma unroll
        for (int kk = 0; kk < 2; kk++) {
            uint32_t ah[2][4], al[2][4];
            #pragma unroll
            for (int mb = 0; mb < 2; mb++) {
                ldsm4(sb + G1_A_HI + aoff[mb] + kk * 32, ah[mb][0], ah[mb][1], ah[mb][2], ah[mb][3]);
                ldsm4(sb + G1_A_LO + aoff[mb] + kk * 32, al[mb][0], al[mb][1], al[mb][2], al[mb][3]);
            }
            #pragma unroll
            for (int nbp = 0; nbp < 4; nbp++) {
                uint32_t bh0, bh1, bh2, bh3, bl0, bl1, bl2, bl3;
                ldsm4(sb + G1_B_HI + boff[nbp] + kk * 32, bh0, bh1, bh2, bh3);
                ldsm4(sb + G1_B_LO + boff[nbp] + kk * 32, bl0, bl1, bl2, bl3);
                #pragma unroll
                for (int mb = 0; mb < 2; mb++) {
                    mma16816(acc[mb][nbp][0], ah[mb], bh0, bh1);
                    mma16816(acc[mb][nbp][0], al[mb], bh0, bh1);
                    mma16816(acc[mb][nbp][0], ah[mb], bl0, bl1);
                    mma16816(acc[mb][nbp][1], ah[mb], bh2, bh3);
                    mma16816(acc[mb][nbp][1], al[mb], bh2, bh3);
                    mma16816(acc[mb][nbp][1], ah[mb], bl2, bl3);
                }
            }
        }
        __syncthreads();
    }

    #pragma unroll
    for (int mb = 0; mb < 2; mb++) {
        #pragma unroll
        for (int nbp = 0; nbp < 4; nbp++) {
            #pragma unroll
            for (int nb = 0; nb < 2; nb++) {
                int n = n0 + wn * 64 + nbp * 16 + nb * 8 + (l & 3) * 2;
                float2 bz = *(const float2*)(g_bias + n);
                int m = m0 + wm * 32 + mb * 16 + (l >> 2);
                float* p0 = g_xw + (size_t)m * NG + n;
                float* p1 = g_xw + (size_t)(m + 8) * NG + n;
                *(float2*)p0 = make_float2(acc[mb][nbp][nb][0] + bz.x, acc[mb][nbp][nb][1] + bz.y);
                *(float2*)p1 = make_float2(acc[mb][nbp][nb][2] + bz.x, acc[mb][nbp][nb][3] + bz.y);
            }
        }
    }
}

// ---------------- Phase 2: persistent recurrence ------------------------------
// 128 CTAs x 256 threads. CTA owns gate-cols [n0, n0+32). Wh slice resident in SMEM.
constexpr int P_SA = 72;                      // A staging stride (elems)
constexpr int P_SB = 1032;                    // resident B stride (elems)
constexpr int P_A_HI = 0;                     // 18432 B
constexpr int P_A_LO = 128 * P_SA * 2;        // 18432
constexpr int P_B_HI = P_A_LO + 128 * P_SA * 2;          // 36864
constexpr int P_B_LO = P_B_HI + 32 * P_SB * 2;           // 102912
constexpr int P_SMEM = P_B_LO + 32 * P_SB * 2;           // 168960
constexpr int PRE_S = 36;

__global__ __launch_bounds__(256)
void lstm_persistent_kernel(float* __restrict__ out, int tail_mode) {
    extern __shared__ char smem[];
    const uint32_t sb = smem_u32(smem);
    const int tid = threadIdx.x, wid = tid >> 5, l = tid & 31;
    const int wm = wid & 3, wn = wid >> 2;
    const int n0 = blockIdx.x * 32;

    // ---- load resident B (Wh slice, hi+lo) into SMEM once ----
    {
        const __nv_bfloat16* srcH = g_WhThi + (size_t)n0 * KDIM;
        const __nv_bfloat16* srcL = g_WhTlo + (size_t)n0 * KDIM;
        for (int idx = tid; idx < 32 * 128; idx += 256) {
            int row = idx >> 7, c16 = idx & 127;
            uint4 vh = *(const uint4*)(srcH + (size_t)row * KDIM + c16 * 8);
            uint4 vl = *(const uint4*)(srcL + (size_t)row * KDIM + c16 * 8);
            *(uint4*)(smem + P_B_HI + (row * P_SB + c16 * 8) * 2) = vh;
            *(uint4*)(smem + P_B_LO + (row * P_SB + c16 * 8) * 2) = vl;
        }
    }
    __syncthreads();

    // ldmatrix offsets
    uint32_t aoff[2];
    #pragma unroll
    for (int mb = 0; mb < 2; mb++)
        aoff[mb] = ((wm * 32 + mb * 16 + (l & 15)) * P_SA + (l >> 4) * 8) * 2;
    const uint32_t boff = ((wn * 16 + (l & 7) + (l >> 4) * 8) * P_SB + ((l >> 3) & 1) * 8) * 2;

    const int ar = tid >> 3, ac = tid & 7;       // A loader mapping
    const int smst = ar * P_SA * 2 + ac * 16;
    float* pre = (float*)smem;                    // epilogue scratch (reuses A region)
    const int u0 = n0 >> 2;

    for (int t = 0; t < T_STEPS; t++) {
        float acc[2][2][4];
        #pragma unroll
        for (int a = 0; a < 2; a++)
            #pragma unroll
            for (int b = 0; b < 2; b++)
                #pragma unroll
                for (int d = 0; d < 4; d++) acc[a][b][d] = 0.f;

        if (t > 0) {
            const __nv_bfloat16* Ahi = g_hhi[t & 1];
            const __nv_bfloat16* Alo = g_hlo[t & 1];
            uint4 pah[4], pal[4];
            auto ld_chunk = [&](int kc) {
                #pragma unroll
                for (int i = 0; i < 4; i++) {
                    size_t ra = (size_t)(ar + 32 * i) * KDIM + kc * 64 + ac * 8;
                    pah[i] = ldcg4(Ahi + ra);
                    pal[i] = ldcg4(Alo + ra);
                }
            };
            ld_chunk(0);
            for (int kc = 0; kc < 16; kc++) {
                #pragma unroll
                for (int i = 0; i < 4; i++) {
                    int o = smst + i * 32 * P_SA * 2;
                    *(uint4*)(smem + P_A_HI + o) = pah[i];
                    *(uint4*)(smem + P_A_LO + o) = pal[i];
                }
                __syncthreads();
                if (kc < 15) ld_chunk(kc + 1);

                #pragma unroll
                for (int kk = 0; kk < 4; kk++) {
                    uint32_t ah[2][4], al[2][4];
                    #pragma unroll
                    for (int mb = 0; mb < 2; mb++) {
                        ldsm4(sb + P_A_HI + aoff[mb] + kk * 32, ah[mb][0], ah[mb][1], ah[mb][2], ah[mb][3]);
                        ldsm4(sb + P_A_LO + aoff[mb] + kk * 32, al[mb][0], al[mb][1], al[mb][2], al[mb][3]);
                    }
                    const uint32_t kb = (uint32_t)(kc * 128 + kk * 32);
                    uint32_t bh0, bh1, bh2, bh3, bl0, bl1, bl2, bl3;
                    ldsm4(sb + P_B_HI + boff + kb, bh0, bh1, bh2, bh3);
                    ldsm4(sb + P_B_LO + boff + kb, bl0, bl1, bl2, bl3);
                    #pragma unroll
                    for (int mb = 0; mb < 2; mb++) {
                        mma16816(acc[mb][0], ah[mb], bh0, bh1);
                        mma16816(acc[mb][0], al[mb], bh0, bh1);
                        mma16816(acc[mb][0], ah[mb], bl0, bl1);
                        mma16816(acc[mb][1], ah[mb], bh2, bh3);
                        mma16816(acc[mb][1], al[mb], bh2, bh3);
                        mma16816(acc[mb][1], ah[mb], bl2, bl3);
                    }
                }
                __syncthreads();
            }
        }

        // dump preactivations to smem (A region is free now)
        #pragma unroll
        for (int mb = 0; mb < 2; mb++) {
            #pragma unroll
            for (int nb = 0; nb < 2; nb++) {
                int row = wm * 32 + mb * 16 + (l >> 2);
                int col = wn * 16 + nb * 8 + (l & 3) * 2;
                *(float2*)(pre + row * PRE_S + col) = make_float2(acc[mb][nb][0], acc[mb][nb][1]);
                *(float2*)(pre + (row + 8) * PRE_S + col) = make_float2(acc[mb][nb][2], acc[mb][nb][3]);
            }
        }
        __syncthreads();

        // fused LSTM epilogue: 1024 cells (128 m x 8 units)
        const int wbuf = (t + 1) & 1;
        #pragma unroll
        for (int i = 0; i < 4; i++) {
            int cell = tid + 256 * i;
            int m = cell >> 3, ul = cell & 7;
            float4 pa = *(const float4*)(pre + m * PRE_S + ul * 4);
            float4 gx = *(const float4*)(g_xw + ((size_t)t * BATCH + m) * NG + n0 + ul * 4);
            float pf = pa.x + gx.x, pi = pa.y + gx.y, pc = pa.z + gx.z, po = pa.w + gx.w;
            float fg = sigmoidf_(pf);
            float ig = sigmoidf_(pi);
            float ct = tanhf(pc);
            float og = sigmoidf_(po);
            int u = u0 + ul;
            int cu = m * HDIM + u;
            float cold = (t > 0) ? g_c[cu] : 0.0f;
            float cn = fg * cold + ig * ct;
            float hn = og * tanhf(cn);
            g_c[cu] = cn;
            out[((size_t)t * BATCH + m) * HDIM + u] = hn;
            __nv_bfloat16 hh = __float2bfloat16(hn);
            __nv_bfloat16 hl = __float2bfloat16(hn - __bfloat162float(hh));
            g_hhi[wbuf][cu] = hh;
            g_hlo[wbuf][cu] = hl;
            if (t == T_STEPS - 1 && tail_mode > 0) {
                size_t TBH = (size_t)T_STEPS * BATCH * HDIM;
                out[TBH + cu] = hn;
                if (tail_mode > 1) out[TBH + (size_t)BATCH * HDIM + cu] = cn;
            }
        }

        // ---- grid barrier (monotonic counter; all CTAs resident) ----
        __syncthreads();
        if (t < T_STEPS - 1) {
            if (tid == 0) {
                __threadfence();
                atomicAdd(&g_bar, 1u);
                const unsigned target = (unsigned)NCTA * (unsigned)(t + 1);
                while (*(volatile unsigned*)&g_bar < target) { __nanosleep(32); }
            }
            __syncthreads();
        }
    }
}

// ---------------- launch ------------------------------------------------------
extern "C" void kernel_launch(void* const* d_in, const int* in_sizes, int n_in,
                              void* d_out, int out_size)
{
    const float* X   = (const float*)d_in[0];
    const float* Wxf = (const float*)d_in[1];
    const float* Whf = (const float*)d_in[2];
    const float* bf  = (const float*)d_in[3];
    const float* Wxi = (const float*)d_in[4];
    const float* Whi = (const float*)d_in[5];
    const float* bi  = (const float*)d_in[6];
    const float* Wxc = (const float*)d_in[7];
    const float* Whc = (const float*)d_in[8];
    const float* bc  = (const float*)d_in[9];
    const float* Wxo = (const float*)d_in[10];
    const float* Who = (const float*)d_in[11];
    const float* bo  = (const float*)d_in[12];
    float* out = (float*)d_out;

    __nv_bfloat16 *wxhi, *wxlo, *whhi, *whlo;
    cudaGetSymbolAddress((void**)&wxhi, g_WxThi);
    cudaGetSymbolAddress((void**)&wxlo, g_WxTlo);
    cudaGetSymbolAddress((void**)&whhi, g_WhThi);
    cudaGetSymbolAddress((void**)&whlo, g_WhTlo);

    cudaFuncSetAttribute(gemm1_kernel, cudaFuncAttributeMaxDynamicSharedMemorySize, G1_SMEM);
    cudaFuncSetAttribute(lstm_persistent_kernel, cudaFuncAttributeMaxDynamicSharedMemorySize, P_SMEM);

    splitx_kernel<<<(TB * KDIM) / 1024, 256>>>(X);
    splitw_kernel<<<dim3(32, 32, 4), 256>>>(Wxf, Wxi, Wxc, Wxo, wxhi, wxlo);
    splitw_kernel<<<dim3(32, 32, 4), 256>>>(Whf, Whi, Whc, Who, whhi, whlo);
    bias_kernel<<<4, 256>>>(bf, bi, bc, bo);  // also zeroes g_bar

    gemm1_kernel<<<dim3(NG / 128, TB / 128), 256, G1_SMEM>>>();

    long long TBH  = (long long)T_STEPS * BATCH * HDIM;
    long long tail = (long long)out_size - TBH;
    int tail_mode = (tail >= 2LL * BATCH * HDIM) ? 2 : (tail >= (long long)BATCH * HDIM) ? 1 : 0;

    lstm_persistent_kernel<<<NCTA, 256, P_SMEM>>>(out, tail_mode);
}

// round 5
// speedup vs baseline: 2.9253x; 1.1627x over previous
#include <cuda_runtime.h>
#include <cuda_bf16.h>
#include <cstdint>

// LSTM T=128, B=128, I=H=1024.  mma.sync bf16 split-precision (3-term).
// Phase 0: split X / W^T (gate-interleaved [n=u*4+g][k]) into bf16 hi/lo; bias.
// Phase 1: g_xw = X @ Wx + b (128x128 tiles, cp.async 2-stage)
// Phase 2: ONE persistent kernel, 128 CTAs, acquire-poll grid barrier per step.
//          Wh slice resident in SMEM; c in registers; cp.async.cg A pipeline.

constexpr int T_STEPS = 128, BATCH = 128, HDIM = 1024, KDIM = 1024;
constexpr int TB = T_STEPS * BATCH;   // 16384
constexpr int NG = 4 * HDIM;          // 4096
constexpr int NCTA = 128;

// ---------------- scratch ----------------------------------------------------
__device__ __nv_bfloat16 g_Xhi[(size_t)TB * KDIM];
__device__ __nv_bfloat16 g_Xlo[(size_t)TB * KDIM];
__device__ __nv_bfloat16 g_WxThi[(size_t)NG * KDIM];
__device__ __nv_bfloat16 g_WxTlo[(size_t)NG * KDIM];
__device__ __nv_bfloat16 g_WhThi[(size_t)NG * KDIM];
__device__ __nv_bfloat16 g_WhTlo[(size_t)NG * KDIM];
__device__ float g_bias[NG];
__device__ float g_xw[(size_t)TB * NG];              // 256 MB
__device__ __nv_bfloat16 g_hhi[2][BATCH * HDIM];
__device__ __nv_bfloat16 g_hlo[2][BATCH * HDIM];
__device__ unsigned g_bar;

// ---------------- helpers ----------------------------------------------------
static __device__ __forceinline__ uint32_t smem_u32(const void* p) {
    uint32_t a;
    asm("{ .reg .u64 t; cvta.to.shared.u64 t, %1; cvt.u32.u64 %0, t; }" : "=r"(a) : "l"(p));
    return a;
}
static __device__ __forceinline__ void ldsm4(uint32_t addr, uint32_t& r0, uint32_t& r1,
                                             uint32_t& r2, uint32_t& r3) {
    asm volatile("ldmatrix.sync.aligned.m8n8.x4.shared.b16 {%0,%1,%2,%3}, [%4];"
                 : "=r"(r0), "=r"(r1), "=r"(r2), "=r"(r3) : "r"(addr));
}
static __device__ __forceinline__ void mma16816(float* d, const uint32_t* a,
                                                uint32_t b0, uint32_t b1) {
    asm volatile(
        "mma.sync.aligned.m16n8k16.row.col.f32.bf16.bf16.f32 "
        "{%0,%1,%2,%3},{%4,%5,%6,%7},{%8,%9},{%0,%1,%2,%3};"
        : "+f"(d[0]), "+f"(d[1]), "+f"(d[2]), "+f"(d[3])
        : "r"(a[0]), "r"(a[1]), "r"(a[2]), "r"(a[3]), "r"(b0), "r"(b1));
}
#define CPA(dst, src) asm volatile("cp.async.cg.shared.global [%0], [%1], 16;" :: "r"(dst), "l"(src))
#define CPC() asm volatile("cp.async.commit_group;" ::: "memory")
#define CPW0() asm volatile("cp.async.wait_group 0;" ::: "memory")
#define CPW1() asm volatile("cp.async.wait_group 1;" ::: "memory")

static __device__ __forceinline__ float sigmoidf_(float x) {
    return __fdividef(1.0f, 1.0f + __expf(-x));
}
static __device__ __forceinline__ float tanh_fast(float x) {
    float a = fabsf(x);
    float z = __expf(-2.0f * a);
    float t = __fdividef(1.0f - z, 1.0f + z);
    return copysignf(t, x);
}

// ---------------- Phase 0 -----------------------------------------------------
__global__ void splitx_kernel(const float* __restrict__ X) {
    size_t i = ((size_t)blockIdx.x * 256 + threadIdx.x) * 4;
    float4 v = *(const float4*)(X + i);
    __nv_bfloat16 h0 = __float2bfloat16(v.x), h1 = __float2bfloat16(v.y);
    __nv_bfloat16 h2 = __float2bfloat16(v.z), h3 = __float2bfloat16(v.w);
    __nv_bfloat16 l0 = __float2bfloat16(v.x - __bfloat162float(h0));
    __nv_bfloat16 l1 = __float2bfloat16(v.y - __bfloat162float(h1));
    __nv_bfloat16 l2 = __float2bfloat16(v.z - __bfloat162float(h2));
    __nv_bfloat16 l3 = __float2bfloat16(v.w - __bfloat162float(h3));
    ((__nv_bfloat162*)(g_Xhi + i))[0] = __nv_bfloat162(h0, h1);
    ((__nv_bfloat162*)(g_Xhi + i))[1] = __nv_bfloat162(h2, h3);
    ((__nv_bfloat162*)(g_Xlo + i))[0] = __nv_bfloat162(l0, l1);
    ((__nv_bfloat162*)(g_Xlo + i))[1] = __nv_bfloat162(l2, l3);
}

__global__ void splitw_kernel(const float* __restrict__ W0, const float* __restrict__ W1,
                              const float* __restrict__ W2, const float* __restrict__ W3,
                              __nv_bfloat16* __restrict__ hiT, __nv_bfloat16* __restrict__ loT) {
    __shared__ float sm[32][33];
    const int g = blockIdx.z;
    const float* W = (g == 0) ? W0 : (g == 1) ? W1 : (g == 2) ? W2 : W3;
    const int k0 = blockIdx.x * 32, u0 = blockIdx.y * 32;
    const int tx = threadIdx.x & 31, ty = threadIdx.x >> 5;
    #pragma unroll
    for (int i = 0; i < 4; i++)
        sm[ty + 8 * i][tx] = W[(size_t)(k0 + ty + 8 * i) * HDIM + u0 + tx];
    __syncthreads();
    #pragma unroll
    for (int i = 0; i < 4; i++) {
        int ul = ty + 8 * i;
        float v = sm[tx][ul];
        __nv_bfloat16 h = __float2bfloat16(v);
        __nv_bfloat16 l = __float2bfloat16(v - __bfloat162float(h));
        size_t n = (size_t)(u0 + ul) * 4 + g;
        hiT[n * KDIM + k0 + tx] = h;
        loT[n * KDIM + k0 + tx] = l;
    }
}

__global__ void bias_kernel(const float* __restrict__ bf, const float* __restrict__ bi,
                            const float* __restrict__ bc, const float* __restrict__ bo) {
    int u = blockIdx.x * 256 + threadIdx.x;
    g_bias[u * 4 + 0] = bf[u];
    g_bias[u * 4 + 1] = bi[u];
    g_bias[u * 4 + 2] = bc[u];
    g_bias[u * 4 + 3] = bo[u];
    if (u == 0) g_bar = 0;
}

// ---------------- Phase 1: GEMM1 (cp.async 2-stage) --------------------------
constexpr int G1_SA = 40;                               // elems
constexpr int G1_MAT = 128 * G1_SA * 2;                 // 10240 B per matrix
constexpr int G1_STAGE = 4 * G1_MAT;                    // 40960 B
constexpr int G1_SMEM = 2 * G1_STAGE;                   // 81920

__global__ __launch_bounds__(256)
void gemm1_kernel() {
    extern __shared__ char smem[];
    const uint32_t sb = smem_u32(smem);
    const int tid = threadIdx.x, wid = tid >> 5, l = tid & 31;
    const int wm = wid & 3, wn = wid >> 2;
    const int n0 = blockIdx.x * 128, m0 = blockIdx.y * 128;

    const int lr = tid >> 2, lc = tid & 3;
    auto issue = [&](int kc, int s) {
        uint32_t base = sb + s * G1_STAGE;
        #pragma unroll
        for (int i = 0; i < 2; i++) {
            int row = lr + 64 * i;
            uint32_t off = (uint32_t)(row * G1_SA + lc * 8) * 2;
            size_t ga = (size_t)(m0 + row) * KDIM + kc * 32 + lc * 8;
            size_t gb = (size_t)(n0 + row) * KDIM + kc * 32 + lc * 8;
            CPA(base + 0 * G1_MAT + off, g_Xhi + ga);
            CPA(base + 1 * G1_MAT + off, g_Xlo + ga);
            CPA(base + 2 * G1_MAT + off, g_WxThi + gb);
            CPA(base + 3 * G1_MAT + off, g_WxTlo + gb);
        }
        CPC();
    };

    uint32_t aoff[2];
    #pragma unroll
    for (int mb = 0; mb < 2; mb++)
        aoff[mb] = ((wm * 32 + mb * 16 + (l & 15)) * G1_SA + (l >> 4) * 8) * 2;
    uint32_t boff[4];
    #pragma unroll
    for (int nbp = 0; nbp < 4; nbp++)
        boff[nbp] = ((wn * 64 + nbp * 16 + (l & 7) + (l >> 4) * 8) * G1_SA +
                     ((l >> 3) & 1) * 8) * 2;

    float acc[2][4][2][4];
    #pragma unroll
    for (int a = 0; a < 2; a++)
        #pragma unroll
        for (int b = 0; b < 4; b++)
            #pragma unroll
            for (int c = 0; c < 2; c++)
                #pragma unroll
                for (int d = 0; d < 4; d++) acc[a][b][c][d] = 0.f;

    issue(0, 0);
    issue(1, 1);
    for (int kc = 0; kc < 32; kc++) {
        if (kc == 31) { CPW0(); } else { CPW1(); }
        __syncthreads();
        const uint32_t base = sb + (kc & 1) * G1_STAGE;
        #pragma unroll
        for (int kk = 0; kk < 2; kk++) {
            uint32_t ah[2][4], al[2][4];
            #pragma unroll
            for (int mb = 0; mb < 2; mb++) {
                ldsm4(base + 0 * G1_MAT + aoff[mb] + kk * 32, ah[mb][0], ah[mb][1], ah[mb][2], ah[mb][3]);
                ldsm4(base + 1 * G1_MAT + aoff[mb] + kk * 32, al[mb][0], al[mb][1], al[mb][2], al[mb][3]);
            }
            #pragma unroll
            for (int nbp = 0; nbp < 4; nbp++) {
                uint32_t bh0, bh1, bh2, bh3, bl0, bl1, bl2, bl3;
                ldsm4(base + 2 * G1_MAT + boff[nbp] + kk * 32, bh0, bh1, bh2, bh3);
                ldsm4(base + 3 * G1_MAT + boff[nbp] + kk * 32, bl0, bl1, bl2, bl3);
                #pragma unroll
                for (int mb = 0; mb < 2; mb++) {
                    mma16816(acc[mb][nbp][0], ah[mb], bh0, bh1);
                    mma16816(acc[mb][nbp][0], al[mb], bh0, bh1);
                    mma16816(acc[mb][nbp][0], ah[mb], bl0, bl1);
                    mma16816(acc[mb][nbp][1], ah[mb], bh2, bh3);
                    mma16816(acc[mb][nbp][1], al[mb], bh2, bh3);
                    mma16816(acc[mb][nbp][1], ah[mb], bl2, bl3);
                }
            }
        }
        __syncthreads();
        if (kc + 2 < 32) issue(kc + 2, kc & 1);
    }

    #pragma unroll
    for (int mb = 0; mb < 2; mb++) {
        #pragma unroll
        for (int nbp = 0; nbp < 4; nbp++) {
            #pragma unroll
            for (int nb = 0; nb < 2; nb++) {
                int n = n0 + wn * 64 + nbp * 16 + nb * 8 + (l & 3) * 2;
                float2 bz = *(const float2*)(g_bias + n);
                int m = m0 + wm * 32 + mb * 16 + (l >> 2);
                float* p0 = g_xw + (size_t)m * NG + n;
                float* p1 = g_xw + (size_t)(m + 8) * NG + n;
                *(float2*)p0 = make_float2(acc[mb][nbp][nb][0] + bz.x, acc[mb][nbp][nb][1] + bz.y);
                *(float2*)p1 = make_float2(acc[mb][nbp][nb][2] + bz.x, acc[mb][nbp][nb][3] + bz.y);
            }
        }
    }
}

// ---------------- Phase 2: persistent recurrence ------------------------------
constexpr int P_SA = 72;                            // elems
constexpr int P_HALF = 128 * P_SA * 2;              // 18432 B (one of hi/lo)
constexpr int P_STAGE = 2 * P_HALF;                 // 36864 B
constexpr int P_SB = 1032;                          // elems
constexpr int P_B_HI = 2 * P_STAGE;                 // 73728
constexpr int P_B_LO = P_B_HI + 32 * P_SB * 2;      // 139776
constexpr int P_SMEM = P_B_LO + 32 * P_SB * 2;      // 205824
constexpr int PRE_S = 36;

__global__ __launch_bounds__(256)
void lstm_persistent_kernel(float* __restrict__ out, int tail_mode) {
    extern __shared__ char smem[];
    const uint32_t sb = smem_u32(smem);
    const int tid = threadIdx.x, wid = tid >> 5, l = tid & 31;
    const int wm = wid & 3, wn = wid >> 2;
    const int n0 = blockIdx.x * 32;

    // resident B (Wh slice hi+lo)
    {
        const __nv_bfloat16* srcH = g_WhThi + (size_t)n0 * KDIM;
        const __nv_bfloat16* srcL = g_WhTlo + (size_t)n0 * KDIM;
        for (int idx = tid; idx < 32 * 128; idx += 256) {
            int row = idx >> 7, c16 = idx & 127;
            uint32_t off = (uint32_t)(row * P_SB + c16 * 8) * 2;
            CPA(sb + P_B_HI + off, srcH + (size_t)row * KDIM + c16 * 8);
            CPA(sb + P_B_LO + off, srcL + (size_t)row * KDIM + c16 * 8);
        }
        CPC(); CPW0();
    }
    __syncthreads();

    uint32_t aoff[2];
    #pragma unroll
    for (int mb = 0; mb < 2; mb++)
        aoff[mb] = ((wm * 32 + mb * 16 + (l & 15)) * P_SA + (l >> 4) * 8) * 2;
    const uint32_t boff = ((wn * 16 + (l & 7) + (l >> 4) * 8) * P_SB + ((l >> 3) & 1) * 8) * 2;

    const int ar = tid >> 3, ac = tid & 7;
    float* pre = (float*)smem;
    const int u0 = n0 >> 2;
    // per-thread cell coords (fixed all steps): 4 cells
    int cm[4], cul[4];
    #pragma unroll
    for (int i = 0; i < 4; i++) { int cell = tid + 256 * i; cm[i] = cell >> 3; cul[i] = cell & 7; }
    float creg[4] = {0.f, 0.f, 0.f, 0.f};

    for (int t = 0; t < T_STEPS; t++) {
        // prefetch g_xw for this step into regs
        float4 gx[4];
        #pragma unroll
        for (int i = 0; i < 4; i++)
            gx[i] = *(const float4*)(g_xw + ((size_t)t * BATCH + cm[i]) * NG + n0 + cul[i] * 4);

        float acc[2][2][4];
        #pragma unroll
        for (int a = 0; a < 2; a++)
            #pragma unroll
            for (int b = 0; b < 2; b++)
                #pragma unroll
                for (int d = 0; d < 4; d++) acc[a][b][d] = 0.f;

        if (t > 0) {
            const __nv_bfloat16* Ahi = g_hhi[t & 1];
            const __nv_bfloat16* Alo = g_hlo[t & 1];
            auto issue = [&](int kc, int s) {
                uint32_t base = sb + s * P_STAGE;
                #pragma unroll
                for (int i = 0; i < 4; i++) {
                    int row = ar + 32 * i;
                    uint32_t off = (uint32_t)(row * P_SA + ac * 8) * 2;
                    size_t ga = (size_t)row * KDIM + kc * 64 + ac * 8;
                    CPA(base + off, Ahi + ga);
                    CPA(base + P_HALF + off, Alo + ga);
                }
                CPC();
            };
            issue(0, 0);
            issue(1, 1);
            for (int kc = 0; kc < 16; kc++) {
                if (kc == 15) { CPW0(); } else { CPW1(); }
                __syncthreads();
                const uint32_t base = sb + (kc & 1) * P_STAGE;
                #pragma unroll
                for (int kk = 0; kk < 4; kk++) {
                    uint32_t ah[2][4], al[2][4];
                    #pragma unroll
                    for (int mb = 0; mb < 2; mb++) {
                        ldsm4(base + aoff[mb] + kk * 32, ah[mb][0], ah[mb][1], ah[mb][2], ah[mb][3]);
                        ldsm4(base + P_HALF + aoff[mb] + kk * 32, al[mb][0], al[mb][1], al[mb][2], al[mb][3]);
                    }
                    const uint32_t kb = (uint32_t)(kc * 128 + kk * 32);
                    uint32_t bh0, bh1, bh2, bh3, bl0, bl1, bl2, bl3;
                    ldsm4(sb + P_B_HI + boff + kb, bh0, bh1, bh2, bh3);
                    ldsm4(sb + P_B_LO + boff + kb, bl0, bl1, bl2, bl3);
                    #pragma unroll
                    for (int mb = 0; mb < 2; mb++) {
                        mma16816(acc[mb][0], ah[mb], bh0, bh1);
                        mma16816(acc[mb][0], al[mb], bh0, bh1);
                        mma16816(acc[mb][0], ah[mb], bl0, bl1);
                        mma16816(acc[mb][1], ah[mb], bh2, bh3);
                        mma16816(acc[mb][1], al[mb], bh2, bh3);
                        mma16816(acc[mb][1], ah[mb], bl2, bl3);
                    }
                }
                __syncthreads();
                if (kc + 2 < 16) issue(kc + 2, kc & 1);
            }
        }

        // dump preactivations (A stage region is free)
        #pragma unroll
        for (int mb = 0; mb < 2; mb++) {
            #pragma unroll
            for (int nb = 0; nb < 2; nb++) {
                int row = wm * 32 + mb * 16 + (l >> 2);
                int col = wn * 16 + nb * 8 + (l & 3) * 2;
                *(float2*)(pre + row * PRE_S + col) = make_float2(acc[mb][nb][0], acc[mb][nb][1]);
                *(float2*)(pre + (row + 8) * PRE_S + col) = make_float2(acc[mb][nb][2], acc[mb][nb][3]);
            }
        }
        __syncthreads();

        const int wbuf = (t + 1) & 1;
        #pragma unroll
        for (int i = 0; i < 4; i++) {
            const int m = cm[i], ul = cul[i];
            float4 pa = *(const float4*)(pre + m * PRE_S + ul * 4);
            float pf = pa.x + gx[i].x, pi = pa.y + gx[i].y;
            float pc = pa.z + gx[i].z, po = pa.w + gx[i].w;
            float fg = sigmoidf_(pf);
            float ig = sigmoidf_(pi);
            float ct = tanh_fast(pc);
            float og = sigmoidf_(po);
            float cn = fg * creg[i] + ig * ct;
            float hn = og * tanh_fast(cn);
            creg[i] = cn;
            const int u = u0 + ul;
            const int cu = m * HDIM + u;
            out[((size_t)t * BATCH + m) * HDIM + u] = hn;
            __nv_bfloat16 hh = __float2bfloat16(hn);
            __nv_bfloat16 hl = __float2bfloat16(hn - __bfloat162float(hh));
            g_hhi[wbuf][cu] = hh;
            g_hlo[wbuf][cu] = hl;
            if (t == T_STEPS - 1 && tail_mode > 0) {
                size_t TBH = (size_t)T_STEPS * BATCH * HDIM;
                out[TBH + cu] = hn;
                if (tail_mode > 1) out[TBH + (size_t)BATCH * HDIM + cu] = cn;
            }
        }

        __syncthreads();
        if (t < T_STEPS - 1) {
            if (tid == 0) {
                __threadfence();
                atomicAdd(&g_bar, 1u);
                const unsigned target = (unsigned)NCTA * (unsigned)(t + 1);
                unsigned v;
                do {
                    asm volatile("ld.global.acquire.gpu.u32 %0, [%1];"
                                 : "=r"(v) : "l"(&g_bar));
                } while (v < target);
            }
            __syncthreads();
        }
    }
}

// ---------------- launch ------------------------------------------------------
extern "C" void kernel_launch(void* const* d_in, const int* in_sizes, int n_in,
                              void* d_out, int out_size)
{
    const float* X   = (const float*)d_in[0];
    const float* Wxf = (const float*)d_in[1];
    const float* Whf = (const float*)d_in[2];
    const float* bf  = (const float*)d_in[3];
    const float* Wxi = (const float*)d_in[4];
    const float* Whi = (const float*)d_in[5];
    const float* bi  = (const float*)d_in[6];
    const float* Wxc = (const float*)d_in[7];
    const float* Whc = (const float*)d_in[8];
    const float* bc  = (const float*)d_in[9];
    const float* Wxo = (const float*)d_in[10];
    const float* Who = (const float*)d_in[11];
    const float* bo  = (const float*)d_in[12];
    float* out = (float*)d_out;

    __nv_bfloat16 *wxhi, *wxlo, *whhi, *whlo;
    cudaGetSymbolAddress((void**)&wxhi, g_WxThi);
    cudaGetSymbolAddress((void**)&wxlo, g_WxTlo);
    cudaGetSymbolAddress((void**)&whhi, g_WhThi);
    cudaGetSymbolAddress((void**)&whlo, g_WhTlo);

    cudaFuncSetAttribute(gemm1_kernel, cudaFuncAttributeMaxDynamicSharedMemorySize, G1_SMEM);
    cudaFuncSetAttribute(lstm_persistent_kernel, cudaFuncAttributeMaxDynamicSharedMemorySize, P_SMEM);

    splitx_kernel<<<(TB * KDIM) / 1024, 256>>>(X);
    splitw_kernel<<<dim3(32, 32, 4), 256>>>(Wxf, Wxi, Wxc, Wxo, wxhi, wxlo);
    splitw_kernel<<<dim3(32, 32, 4), 256>>>(Whf, Whi, Whc, Who, whhi, whlo);
    bias_kernel<<<4, 256>>>(bf, bi, bc, bo);  // also zeroes g_bar

    gemm1_kernel<<<dim3(NG / 128, TB / 128), 256, G1_SMEM>>>();

    long long TBH  = (long long)T_STEPS * BATCH * HDIM;
    long long tail = (long long)out_size - TBH;
    int tail_mode = (tail >= 2LL * BATCH * HDIM) ? 2 : (tail >= (long long)BATCH * HDIM) ? 1 : 0;

    lstm_persistent_kernel<<<NCTA, 256, P_SMEM>>>(out, tail_mode);
}